// round 1
// baseline (speedup 1.0000x reference)
#include <cuda_runtime.h>
#include <cstdint>

#define N_FEAT   128
#define N_CLUS   64
#define TILE_M   128
#define THREADS  256
#define XSTRIDE  132          // floats per smem row (528 B): bank stride 4, conflict-free pattern
#define GRID_MAIN 148

// global scratch (allowed: static __device__, no allocation)
__device__ unsigned long long g_best[N_CLUS];

// ---------- helpers ----------
__device__ __forceinline__ unsigned int orderf(float f) {
    unsigned int u = __float_as_uint(f);
    return (u & 0x80000000u) ? ~u : (u | 0x80000000u);   // monotonic float->uint
}
__device__ __forceinline__ unsigned long long pack2(float lo, float hi) {
    unsigned long long r;
    asm("mov.b64 %0, {%1, %2};" : "=l"(r) : "f"(lo), "f"(hi));
    return r;
}
__device__ __forceinline__ void unpack2(unsigned long long v, float& lo, float& hi) {
    asm("mov.b64 {%0, %1}, %2;" : "=f"(lo), "=f"(hi) : "l"(v));
}
__device__ __forceinline__ void fma2(unsigned long long& acc, unsigned long long a, unsigned long long b) {
    asm("fma.rn.f32x2 %0, %1, %2, %0;" : "+l"(acc) : "l"(a), "l"(b));
}
__device__ __forceinline__ void cp16(uint32_t s, const void* g) {
    asm volatile("cp.async.cg.shared.global [%0], [%1], 16;" :: "r"(s), "l"(g));
}
__device__ __forceinline__ void cp_commit() { asm volatile("cp.async.commit_group;"); }
__device__ __forceinline__ void cp_wait1() { asm volatile("cp.async.wait_group 1;" ::: "memory"); }

__device__ __forceinline__ void prefetch_tile(const float* __restrict__ x, int base, int n_tokens,
                                              char* bufp, int tid) {
    uint32_t sb = (uint32_t)__cvta_generic_to_shared(bufp);
#pragma unroll
    for (int c = 0; c < 16; ++c) {
        int chunk = tid + c * THREADS;          // 0..4095
        int r = chunk >> 5, q = chunk & 31;     // row, 16B-chunk
        if (base + r < n_tokens)
            cp16(sb + (uint32_t)(r * (XSTRIDE * 4) + q * 16),
                 x + (size_t)(base + r) * N_FEAT + q * 4);
    }
}

// ---------- main kernel ----------
extern __shared__ char smem[];

__global__ void __launch_bounds__(THREADS, 1)
cluster_main(const float* __restrict__ x, const float* __restrict__ cc, int n_tokens)
{
    float* xbuf = (float*)smem;                                    // 2 * 128 * 132 floats = 135168 B
    float* cd   = (float*)(smem + 2 * TILE_M * XSTRIDE * 4);       // 128 * 64 float2 = 65536 B (dup centers)
    float* x2s  = (float*)(smem + 2 * TILE_M * XSTRIDE * 4 + N_FEAT * N_CLUS * 8);  // 512 B
    unsigned long long* red = (unsigned long long*)smem;           // aliases xbuf (only used at the very end)

    const int tid = threadIdx.x;
    const int tc  = tid & 7;     // cluster-group 0..7  -> clusters [8*tc, 8*tc+8)
    const int tg  = tid >> 3;    // token-group   0..31 -> tokens tg + 32*i, i=0..3

    const int NT = (n_tokens + TILE_M - 1) / TILE_M;

    // kick off first tile load ASAP
    int t = blockIdx.x;
    if (t < NT) prefetch_tile(x, t * TILE_M, n_tokens, (char*)xbuf, tid);
    cp_commit();

    // build duplicated-center smem: cluster k -> (tco=k>>3, p=k&7, j=p>>1, m=p&1)
    // float2(c,c) at float-offset d*128 + j*32 + tco*4 + m*2  (byte: d*512 + j*128 + tco*16 + m*8)
    for (int i = tid; i < N_CLUS * N_FEAT; i += THREADS) {
        int k = i >> 7;
        int d = i & 127;
        float v = cc[k * N_FEAT + d];
        int j = (k & 7) >> 1, tco = k >> 3, m = k & 1;
        int fo = d * 128 + j * 32 + tco * 4 + m * 2;
        cd[fo] = v; cd[fo + 1] = v;
    }
    __syncthreads();

    unsigned long long best[8];
#pragma unroll
    for (int k = 0; k < 8; ++k) best[k] = 0ull;

    int it = 0;
    for (; t < NT; t += GRID_MAIN, ++it) {
        float* cur = xbuf + (it & 1) * (TILE_M * XSTRIDE);
        float* nxt = xbuf + ((it + 1) & 1) * (TILE_M * XSTRIDE);

        int tn = t + GRID_MAIN;
        if (tn < NT) prefetch_tile(x, tn * TILE_M, n_tokens, (char*)nxt, tid);
        cp_commit();
        cp_wait1();              // oldest group (tile t) retired
        __syncthreads();

        const int base = t * TILE_M;

        // per-token |x|^2 (re-read from global; tile is L2-hot from the cp.async.cg)
        if (tid < TILE_M) {
            float s = 0.f;
            if (base + tid < n_tokens) {
                const float4* g = (const float4*)(x + (size_t)(base + tid) * N_FEAT);
                float s0 = 0.f, s1 = 0.f, s2 = 0.f, s3 = 0.f;
#pragma unroll
                for (int q = 0; q < 32; q += 4) {
                    float4 a = g[q], b = g[q + 1], c = g[q + 2], d = g[q + 3];
                    s0 += a.x * a.x + a.y * a.y + a.z * a.z + a.w * a.w;
                    s1 += b.x * b.x + b.y * b.y + b.z * b.z + b.w * b.w;
                    s2 += c.x * c.x + c.y * c.y + c.z * c.z + c.w * c.w;
                    s3 += d.x * d.x + d.y * d.y + d.z * d.z + d.w * d.w;
                }
                s = (s0 + s1) + (s2 + s3);
            }
            x2s[tid] = s;
        }
        __syncthreads();

        // 8 tokens (4 f32x2 pairs... 2 pairs here: (tg,tg+32),(tg+64,tg+96)) x 8 clusters
        unsigned long long acc[16];
        const unsigned long long z = pack2(0.f, 0.f);
#pragma unroll
        for (int i = 0; i < 16; ++i) acc[i] = z;

#pragma unroll 4
        for (int d = 0; d < N_FEAT; ++d) {
            float a0 = cur[(tg      ) * XSTRIDE + d];
            float a1 = cur[(tg + 32 ) * XSTRIDE + d];
            float a2 = cur[(tg + 64 ) * XSTRIDE + d];
            float a3 = cur[(tg + 96 ) * XSTRIDE + d];
            unsigned long long p0 = pack2(a0, a1);
            unsigned long long p1 = pack2(a2, a3);
            const ulonglong2* cp = (const ulonglong2*)(cd + d * 128 + tc * 4);
#pragma unroll
            for (int j = 0; j < 4; ++j) {
                ulonglong2 cv = cp[j * 8];       // +j*128 B
                fma2(acc[2 * j    ], p0, cv.x);
                fma2(acc[2 * j + 1], p0, cv.y);
                fma2(acc[8 + 2 * j    ], p1, cv.x);
                fma2(acc[8 + 2 * j + 1], p1, cv.y);
            }
        }

        // epilogue: score = x.c - 0.5*|x|^2 ; keep running per-cluster best in registers
        float xl0 = x2s[tg], xl1 = x2s[tg + 32], xl2 = x2s[tg + 64], xl3 = x2s[tg + 96];
#pragma unroll
        for (int kc = 0; kc < 8; ++kc) {
            float f0, f1, f2, f3;
            unpack2(acc[kc],     f0, f1);
            unpack2(acc[8 + kc], f2, f3);
            float sc0 = f0 - 0.5f * xl0;
            float sc1 = f1 - 0.5f * xl1;
            float sc2 = f2 - 0.5f * xl2;
            float sc3 = f3 - 0.5f * xl3;
            float scs[4] = {sc0, sc1, sc2, sc3};
#pragma unroll
            for (int i = 0; i < 4; ++i) {
                unsigned int gi = (unsigned int)(base + tg + 32 * i);
                if (gi < (unsigned int)n_tokens) {
                    unsigned long long key =
                        ((unsigned long long)orderf(scs[i]) << 32) |
                        (unsigned long long)(0xFFFFFFFFu - gi);   // bigger key = better score, then smaller idx
                    if (key > best[kc]) best[kc] = key;
                }
            }
        }
        __syncthreads();   // before next iteration's prefetch overwrites `cur`
    }

    // CTA reduction (red aliases xbuf; all tile work done)
    __syncthreads();
#pragma unroll
    for (int kc = 0; kc < 8; ++kc)
        red[(8 * tc + kc) * 32 + tg] = best[kc];
    __syncthreads();
    if (tid < N_CLUS) {
        unsigned long long m = 0ull;
#pragma unroll 8
        for (int i = 0; i < 32; ++i) {
            unsigned long long v = red[tid * 32 + i];
            if (v > m) m = v;
        }
        atomicMax(&g_best[tid], m);
    }
}

// ---------- init / gather ----------
__global__ void init_kernel() {
    g_best[threadIdx.x] = 0ull;
}

__global__ void gather_kernel(const float* __restrict__ x, float* __restrict__ out) {
    unsigned int gi = 0xFFFFFFFFu - (unsigned int)(g_best[blockIdx.x] & 0xFFFFFFFFull);
    out[blockIdx.x * N_FEAT + threadIdx.x] = x[(size_t)gi * N_FEAT + threadIdx.x];
}

// ---------- launch ----------
extern "C" void kernel_launch(void* const* d_in, const int* in_sizes, int n_in,
                              void* d_out, int out_size)
{
    const float* x  = (const float*)d_in[0];
    const float* cc = (const float*)d_in[1];
    int n_tokens = in_sizes[0] / N_FEAT;

    size_t smem_bytes = (size_t)(2 * TILE_M * XSTRIDE * 4)   // x double buffer
                      + (size_t)(N_FEAT * N_CLUS * 8)        // duplicated centers
                      + (size_t)(TILE_M * 4);                // x2
    cudaFuncSetAttribute(cluster_main, cudaFuncAttributeMaxDynamicSharedMemorySize, (int)smem_bytes);

    init_kernel<<<1, N_CLUS>>>();
    cluster_main<<<GRID_MAIN, THREADS, smem_bytes>>>(x, cc, n_tokens);
    gather_kernel<<<N_CLUS, N_FEAT>>>(x, (float*)d_out);
}

// round 3
// speedup vs baseline: 2.7296x; 2.7296x over previous
#include <cuda_runtime.h>
#include <cuda_bf16.h>
#include <cstdint>

#define N_FEAT    128
#define N_CLUS    64
#define TILE_M    128
#define THREADS   256
#define GRID_MAIN 148

// smem layout (bytes)
#define OFF_XHI   0          // 128 rows * 256B (bf16, swizzled)
#define OFF_XLO   32768
#define OFF_BHI   65536      // 64 rows * 256B
#define OFF_BLO   81920
#define OFF_X2    98304      // 128 floats
#define OFF_BEST  98816      // 64 u64
#define SMEM_TOTAL 99328

__device__ unsigned long long g_part[GRID_MAIN * N_CLUS];

// ---------------- helpers ----------------
__device__ __forceinline__ uint32_t smem_u32(const void* p) {
    return (uint32_t)__cvta_generic_to_shared(p);
}
__device__ __forceinline__ uint32_t prmt_hi(uint32_t a, uint32_t b) {
    uint32_t d;
    asm("prmt.b32 %0, %1, %2, 0x7632;" : "=r"(d) : "r"(a), "r"(b)); // lo16=a>>16, hi16=b>>16
    return d;
}
__device__ __forceinline__ uint32_t cvt_bf2(float hi, float lo) {
    uint32_t d;
    asm("cvt.rn.bf16x2.f32 %0, %1, %2;" : "=r"(d) : "f"(hi), "f"(lo)); // low half = lo
    return d;
}
__device__ __forceinline__ uint32_t orderf(float f) {
    uint32_t u = __float_as_uint(f);
    return u ^ (((uint32_t)((int32_t)u >> 31)) | 0x80000000u);
}
__device__ __forceinline__ void sts128(uint32_t a, uint32_t x, uint32_t y, uint32_t z, uint32_t w) {
    asm volatile("st.shared.v4.b32 [%0], {%1,%2,%3,%4};" :: "r"(a), "r"(x), "r"(y), "r"(z), "r"(w) : "memory");
}
__device__ __forceinline__ void ldm4(uint32_t& r0, uint32_t& r1, uint32_t& r2, uint32_t& r3, uint32_t a) {
    asm volatile("ldmatrix.sync.aligned.m8n8.x4.shared.b16 {%0,%1,%2,%3}, [%4];"
                 : "=r"(r0), "=r"(r1), "=r"(r2), "=r"(r3) : "r"(a));
}
__device__ __forceinline__ void mma16816(float& c0, float& c1, float& c2, float& c3,
                                         uint32_t a0, uint32_t a1, uint32_t a2, uint32_t a3,
                                         uint32_t b0, uint32_t b1) {
    asm volatile("mma.sync.aligned.m16n8k16.row.col.f32.bf16.bf16.f32 "
                 "{%0,%1,%2,%3},{%4,%5,%6,%7},{%8,%9},{%0,%1,%2,%3};"
                 : "+f"(c0), "+f"(c1), "+f"(c2), "+f"(c3)
                 : "r"(a0), "r"(a1), "r"(a2), "r"(a3), "r"(b0), "r"(b1));
}
// convert 8 floats -> hi uint4 + lo uint4 (bf16 pairs), accumulate squares
__device__ __forceinline__ void conv8(const float4& a, const float4& b,
                                      uint32_t h[4], uint32_t l[4], float& s) {
    uint32_t u0 = __float_as_uint(a.x), u1 = __float_as_uint(a.y);
    uint32_t u2 = __float_as_uint(a.z), u3 = __float_as_uint(a.w);
    uint32_t u4 = __float_as_uint(b.x), u5 = __float_as_uint(b.y);
    uint32_t u6 = __float_as_uint(b.z), u7 = __float_as_uint(b.w);
    h[0] = prmt_hi(u0, u1); h[1] = prmt_hi(u2, u3);
    h[2] = prmt_hi(u4, u5); h[3] = prmt_hi(u6, u7);
    float r0 = a.x - __uint_as_float(u0 & 0xFFFF0000u);
    float r1 = a.y - __uint_as_float(u1 & 0xFFFF0000u);
    float r2 = a.z - __uint_as_float(u2 & 0xFFFF0000u);
    float r3 = a.w - __uint_as_float(u3 & 0xFFFF0000u);
    float r4 = b.x - __uint_as_float(u4 & 0xFFFF0000u);
    float r5 = b.y - __uint_as_float(u5 & 0xFFFF0000u);
    float r6 = b.z - __uint_as_float(u6 & 0xFFFF0000u);
    float r7 = b.w - __uint_as_float(u7 & 0xFFFF0000u);
    l[0] = cvt_bf2(r1, r0); l[1] = cvt_bf2(r3, r2);
    l[2] = cvt_bf2(r5, r4); l[3] = cvt_bf2(r7, r6);
    s += a.x * a.x + a.y * a.y + a.z * a.z + a.w * a.w;
    s += b.x * b.x + b.y * b.y + b.z * b.z + b.w * b.w;
}

extern __shared__ char smem[];

__global__ void __launch_bounds__(THREADS, 1)
cluster_hmma(const float* __restrict__ x, const float* __restrict__ cc, int n_tokens)
{
    const int tid  = threadIdx.x;
    const int lane = tid & 31;
    const int wid  = tid >> 5;
    const int mg   = wid >> 1;     // m-group: rows [mg*32, mg*32+32)
    const int nh   = wid & 1;      // n-half:  cols [nh*32, nh*32+32)
    const int bid  = blockIdx.x;
    const uint32_t sb = smem_u32(smem);
    const int NT = (n_tokens + TILE_M - 1) / TILE_M;

    const int crow = tid >> 1, chalf = tid & 1;   // convert mapping: 2 threads/row

    float4 v[16];
#define LOADV(tt) do { \
        long grow_ = (long)(tt) * TILE_M + crow; \
        bool val_ = ((tt) < NT) && (grow_ < (long)n_tokens); \
        const float4* gp_ = (const float4*)(x + (size_t)grow_ * N_FEAT) + chalf * 16; \
        _Pragma("unroll") \
        for (int j_ = 0; j_ < 16; ++j_) \
            v[j_] = val_ ? gp_[j_] : make_float4(0.f, 0.f, 0.f, 0.f); \
    } while (0)

    // prologue: start loading tile `bid` immediately
    LOADV(bid);

    // ---- build centers hi/lo in smem (swizzled [n][k] bf16) ----
#pragma unroll
    for (int i = tid; i < N_CLUS * 16; i += THREADS) {     // 16 chunks of 8 per row
        int n = i >> 4, kc = i & 15;
        const float4* cp = (const float4*)(cc + n * N_FEAT + kc * 8);
        float4 ca = cp[0], cb = cp[1];
        uint32_t h[4], l[4]; float dummy = 0.f;
        conv8(ca, cb, h, l, dummy);
        uint32_t off = (uint32_t)(n * 256 + ((kc * 16) ^ ((n & 7) << 4)));
        sts128(sb + OFF_BHI + off, h[0], h[1], h[2], h[3]);
        sts128(sb + OFF_BLO + off, l[0], l[1], l[2], l[3]);
    }
    if (tid < N_CLUS) ((unsigned long long*)(smem + OFF_BEST))[tid] = 0ull;
    __syncthreads();

    // ---- preload Bhi fragments into registers (constant across all tiles) ----
    const int lr = (lane & 7) | (lane & 8);    // ldmatrix row-within-16
    const int lk = lane & 16;                  // 16B column select
    const uint32_t sw = (uint32_t)((lr & 7) << 4);
    const int nb = nh * 32;

    uint32_t bhi[8][4][2];
#pragma unroll
    for (int ks = 0; ks < 8; ++ks) {
#pragma unroll
        for (int np = 0; np < 2; ++np) {
            uint32_t addr = sb + OFF_BHI + (uint32_t)((nb + np * 16 + lr) * 256)
                          + (((uint32_t)(ks * 32 + lk)) ^ sw);
            uint32_t r0, r1, r2, r3;
            ldm4(r0, r1, r2, r3, addr);
            bhi[ks][np * 2][0] = r0;  bhi[ks][np * 2 + 1][0] = r1;
            bhi[ks][np * 2][1] = r2;  bhi[ks][np * 2 + 1][1] = r3;
        }
    }

    // per-tile-constant ldmatrix base addresses
    uint32_t aAh[2], aAl[2], aBl[2];
#pragma unroll
    for (int mi = 0; mi < 2; ++mi) {
        aAh[mi] = sb + OFF_XHI + (uint32_t)((mg * 32 + mi * 16 + lr) * 256);
        aAl[mi] = sb + OFF_XLO + (uint32_t)((mg * 32 + mi * 16 + lr) * 256);
    }
#pragma unroll
    for (int np = 0; np < 2; ++np)
        aBl[np] = sb + OFF_BLO + (uint32_t)((nb + np * 16 + lr) * 256);

    float* x2s = (float*)(smem + OFF_X2);
    unsigned long long* bestk = (unsigned long long*)(smem + OFF_BEST);

    unsigned long long bests[4][2];
#pragma unroll
    for (int ni = 0; ni < 4; ++ni) { bests[ni][0] = 0ull; bests[ni][1] = 0ull; }

    for (int t = bid; t < NT; t += GRID_MAIN) {
        const int base = t * TILE_M;

        // ---- convert phase: v -> bf16 hi/lo smem + |x|^2 ----
        {
            float s = 0.f;
#pragma unroll
            for (int j = 0; j < 8; ++j) {
                uint32_t h[4], l[4];
                conv8(v[2 * j], v[2 * j + 1], h, l, s);
                uint32_t off = (uint32_t)(crow * 256 + (((chalf * 8 + j) * 16) ^ ((crow & 7) << 4)));
                sts128(sb + OFF_XHI + off, h[0], h[1], h[2], h[3]);
                sts128(sb + OFF_XLO + off, l[0], l[1], l[2], l[3]);
            }
            s += __shfl_xor_sync(0xFFFFFFFFu, s, 1);
            if (chalf == 0) x2s[crow] = s;
        }
        __syncthreads();

        // ---- MMA phase ----
        float c[2][4][4];
#pragma unroll
        for (int mi = 0; mi < 2; ++mi)
#pragma unroll
            for (int ni = 0; ni < 4; ++ni)
#pragma unroll
                for (int r = 0; r < 4; ++r) c[mi][ni][r] = 0.f;

#pragma unroll
        for (int ks = 0; ks < 8; ++ks) {
            const uint32_t ko = ((uint32_t)(ks * 32 + lk)) ^ sw;
            uint32_t ah[2][4], al[2][4];
#pragma unroll
            for (int mi = 0; mi < 2; ++mi) {
                ldm4(ah[mi][0], ah[mi][1], ah[mi][2], ah[mi][3], aAh[mi] + ko);
                ldm4(al[mi][0], al[mi][1], al[mi][2], al[mi][3], aAl[mi] + ko);
            }
            uint32_t bl[4][2];
#pragma unroll
            for (int np = 0; np < 2; ++np) {
                uint32_t r0, r1, r2, r3;
                ldm4(r0, r1, r2, r3, aBl[np] + ko);
                bl[np * 2][0] = r0;  bl[np * 2 + 1][0] = r1;
                bl[np * 2][1] = r2;  bl[np * 2 + 1][1] = r3;
            }
#pragma unroll
            for (int mi = 0; mi < 2; ++mi) {
#pragma unroll
                for (int ni = 0; ni < 4; ++ni) {
                    mma16816(c[mi][ni][0], c[mi][ni][1], c[mi][ni][2], c[mi][ni][3],
                             ah[mi][0], ah[mi][1], ah[mi][2], ah[mi][3],
                             bhi[ks][ni][0], bhi[ks][ni][1]);                 // hh
                    mma16816(c[mi][ni][0], c[mi][ni][1], c[mi][ni][2], c[mi][ni][3],
                             al[mi][0], al[mi][1], al[mi][2], al[mi][3],
                             bhi[ks][ni][0], bhi[ks][ni][1]);                 // lh
                    mma16816(c[mi][ni][0], c[mi][ni][1], c[mi][ni][2], c[mi][ni][3],
                             ah[mi][0], ah[mi][1], ah[mi][2], ah[mi][3],
                             bl[ni][0], bl[ni][1]);                           // hl
                }
            }
        }

        // issue next tile's global loads (hidden behind epilogue + next convert)
        LOADV(t + GRID_MAIN);

        // ---- epilogue: fold into per-thread running bests ----
        float h2[2][2];
#pragma unroll
        for (int mi = 0; mi < 2; ++mi)
#pragma unroll
            for (int p = 0; p < 2; ++p)
                h2[mi][p] = 0.5f * x2s[mg * 32 + mi * 16 + (lane >> 2) + p * 8];

#pragma unroll
        for (int ni = 0; ni < 4; ++ni) {
#pragma unroll
            for (int ci = 0; ci < 2; ++ci) {
                unsigned long long bk = bests[ni][ci];
#pragma unroll
                for (int mi = 0; mi < 2; ++mi) {
#pragma unroll
                    for (int p = 0; p < 2; ++p) {
                        int row = mg * 32 + mi * 16 + (lane >> 2) + p * 8;
                        int gidx = base + row;
                        float sc = c[mi][ni][ci + 2 * p] - h2[mi][p];
                        if (gidx < n_tokens) {
                            unsigned long long key =
                                ((unsigned long long)orderf(sc) << 32) |
                                (unsigned long long)(0xFFFFFFFFu - (uint32_t)gidx);
                            if (key > bk) bk = key;
                        }
                    }
                }
                bests[ni][ci] = bk;
            }
        }
        __syncthreads();   // protect smem tiles + x2s before next convert
    }

    // ---- final reduction: butterfly within column class, atomicMax into smem ----
#pragma unroll
    for (int ni = 0; ni < 4; ++ni) {
#pragma unroll
        for (int ci = 0; ci < 2; ++ci) {
            unsigned long long k = bests[ni][ci];
#pragma unroll
            for (int d = 4; d <= 16; d <<= 1) {
                unsigned long long o = __shfl_xor_sync(0xFFFFFFFFu, k, d);
                if (o > k) k = o;
            }
            if (lane < 4)
                atomicMax(&bestk[nb + ni * 8 + lane * 2 + ci], k);
        }
    }
    __syncthreads();
    if (tid < N_CLUS)
        g_part[(size_t)bid * N_CLUS + tid] = bestk[tid];
}

// ---------------- gather: reduce partials, copy winning rows ----------------
__global__ void gather_k(const float* __restrict__ x, float* __restrict__ out) {
    __shared__ unsigned long long red[256];
    const int c = blockIdx.x, tid = threadIdx.x;
    unsigned long long v = 0ull;
    if (tid < GRID_MAIN) v = g_part[(size_t)tid * N_CLUS + c];
    red[tid] = v;
    __syncthreads();
#pragma unroll
    for (int s = 128; s > 0; s >>= 1) {
        if (tid < s) { unsigned long long o = red[tid + s]; if (o > red[tid]) red[tid] = o; }
        __syncthreads();
    }
    unsigned int gi = 0xFFFFFFFFu - (unsigned int)(red[0] & 0xFFFFFFFFull);
    if (tid < N_FEAT)
        out[c * N_FEAT + tid] = x[(size_t)gi * N_FEAT + tid];
}

// ---------------- launch ----------------
extern "C" void kernel_launch(void* const* d_in, const int* in_sizes, int n_in,
                              void* d_out, int out_size)
{
    const float* x  = (const float*)d_in[0];
    const float* cc = (const float*)d_in[1];
    int n_tokens = in_sizes[0] / N_FEAT;

    cudaFuncSetAttribute(cluster_hmma, cudaFuncAttributeMaxDynamicSharedMemorySize, SMEM_TOTAL);
    cluster_hmma<<<GRID_MAIN, THREADS, SMEM_TOTAL>>>(x, cc, n_tokens);
    gather_k<<<N_CLUS, 256>>>(x, (float*)d_out);
}

// round 4
// speedup vs baseline: 3.8607x; 1.4144x over previous
#include <cuda_runtime.h>
#include <cuda_bf16.h>
#include <cstdint>

#define N_FEAT    128
#define N_CLUS    64
#define TILE_M    128
#define THREADS   256
#define GRID_MAIN 148

// smem layout (bytes)
#define OFF_STAGE 0          // 2 * 128 rows * 512B fp32, XOR-swizzled 16B chunks
#define OFF_XHI   131072     // 128 rows * 256B bf16, swizzled
#define OFF_XLO   163840
#define OFF_BHI   196608     // 64 rows * 256B bf16, swizzled
#define OFF_BLO   212992
#define OFF_X2    229376     // 128 floats
#define OFF_BEST  229888     // 64 u64
#define SMEM_TOTAL 230400

__device__ unsigned long long g_part[GRID_MAIN * N_CLUS];

// ---------------- helpers ----------------
__device__ __forceinline__ uint32_t smem_u32(const void* p) {
    return (uint32_t)__cvta_generic_to_shared(p);
}
__device__ __forceinline__ uint32_t prmt_hi(uint32_t a, uint32_t b) {
    uint32_t d;
    asm("prmt.b32 %0, %1, %2, 0x7632;" : "=r"(d) : "r"(a), "r"(b)); // lo16=a>>16, hi16=b>>16
    return d;
}
__device__ __forceinline__ uint32_t cvt_bf2(float hi, float lo) {
    uint32_t d;
    asm("cvt.rn.bf16x2.f32 %0, %1, %2;" : "=r"(d) : "f"(hi), "f"(lo)); // low half = lo
    return d;
}
__device__ __forceinline__ uint32_t orderf(float f) {
    uint32_t u = __float_as_uint(f);
    return u ^ (((uint32_t)((int32_t)u >> 31)) | 0x80000000u);
}
__device__ __forceinline__ void sts128(uint32_t a, uint32_t x, uint32_t y, uint32_t z, uint32_t w) {
    asm volatile("st.shared.v4.b32 [%0], {%1,%2,%3,%4};" :: "r"(a), "r"(x), "r"(y), "r"(z), "r"(w) : "memory");
}
__device__ __forceinline__ void lds128(float& x, float& y, float& z, float& w, uint32_t a) {
    asm volatile("ld.shared.v4.f32 {%0,%1,%2,%3}, [%4];"
                 : "=f"(x), "=f"(y), "=f"(z), "=f"(w) : "r"(a));
}
__device__ __forceinline__ void ldm4(uint32_t& r0, uint32_t& r1, uint32_t& r2, uint32_t& r3, uint32_t a) {
    asm volatile("ldmatrix.sync.aligned.m8n8.x4.shared.b16 {%0,%1,%2,%3}, [%4];"
                 : "=r"(r0), "=r"(r1), "=r"(r2), "=r"(r3) : "r"(a));
}
__device__ __forceinline__ void mma16816(float& c0, float& c1, float& c2, float& c3,
                                         uint32_t a0, uint32_t a1, uint32_t a2, uint32_t a3,
                                         uint32_t b0, uint32_t b1) {
    asm volatile("mma.sync.aligned.m16n8k16.row.col.f32.bf16.bf16.f32 "
                 "{%0,%1,%2,%3},{%4,%5,%6,%7},{%8,%9},{%0,%1,%2,%3};"
                 : "+f"(c0), "+f"(c1), "+f"(c2), "+f"(c3)
                 : "r"(a0), "r"(a1), "r"(a2), "r"(a3), "r"(b0), "r"(b1));
}
__device__ __forceinline__ void cp16(uint32_t s, const void* g) {
    asm volatile("cp.async.cg.shared.global [%0], [%1], 16;" :: "r"(s), "l"(g));
}
__device__ __forceinline__ void cp_commit() { asm volatile("cp.async.commit_group;"); }
__device__ __forceinline__ void cp_wait0()  { asm volatile("cp.async.wait_group 0;" ::: "memory"); }

// convert 8 floats -> hi uint4 + lo uint4 (bf16 pairs), accumulate squares
__device__ __forceinline__ void conv8(const float4& a, const float4& b,
                                      uint32_t h[4], uint32_t l[4], float& s) {
    uint32_t u0 = __float_as_uint(a.x), u1 = __float_as_uint(a.y);
    uint32_t u2 = __float_as_uint(a.z), u3 = __float_as_uint(a.w);
    uint32_t u4 = __float_as_uint(b.x), u5 = __float_as_uint(b.y);
    uint32_t u6 = __float_as_uint(b.z), u7 = __float_as_uint(b.w);
    h[0] = prmt_hi(u0, u1); h[1] = prmt_hi(u2, u3);
    h[2] = prmt_hi(u4, u5); h[3] = prmt_hi(u6, u7);
    float r0 = a.x - __uint_as_float(u0 & 0xFFFF0000u);
    float r1 = a.y - __uint_as_float(u1 & 0xFFFF0000u);
    float r2 = a.z - __uint_as_float(u2 & 0xFFFF0000u);
    float r3 = a.w - __uint_as_float(u3 & 0xFFFF0000u);
    float r4 = b.x - __uint_as_float(u4 & 0xFFFF0000u);
    float r5 = b.y - __uint_as_float(u5 & 0xFFFF0000u);
    float r6 = b.z - __uint_as_float(u6 & 0xFFFF0000u);
    float r7 = b.w - __uint_as_float(u7 & 0xFFFF0000u);
    l[0] = cvt_bf2(r1, r0); l[1] = cvt_bf2(r3, r2);
    l[2] = cvt_bf2(r5, r4); l[3] = cvt_bf2(r7, r6);
    s += a.x * a.x + a.y * a.y + a.z * a.z + a.w * a.w;
    s += b.x * b.x + b.y * b.y + b.z * b.z + b.w * b.w;
}

extern __shared__ char smem[];

// prefetch one 128x128 fp32 tile into stage buffer b via cp.async
__device__ __forceinline__ void prefetch(const float* __restrict__ x, int t, int NT,
                                         int n_tokens, int b, int tid, uint32_t sb) {
    if (t < NT) {
        const int base = t * TILE_M;
#pragma unroll
        for (int c = 0; c < 16; ++c) {
            int chunk = tid + c * THREADS;      // 0..4095
            int r = chunk >> 5, q = chunk & 31;
            if (base + r < n_tokens)
                cp16(sb + (uint32_t)(OFF_STAGE + b * 65536 + r * 512 + ((q ^ (r & 31)) << 4)),
                     x + (size_t)(base + r) * N_FEAT + q * 4);
        }
    }
    cp_commit();
}

__global__ void __launch_bounds__(THREADS, 1)
cluster_hmma(const float* __restrict__ x, const float* __restrict__ cc, int n_tokens)
{
    const int tid  = threadIdx.x;
    const int lane = tid & 31;
    const int wid  = tid >> 5;
    const int mg   = wid >> 1;     // m-group: rows [mg*32, mg*32+32)
    const int nh   = wid & 1;      // n-half:  cols [nh*32, nh*32+32)
    const int bid  = blockIdx.x;
    const uint32_t sb = smem_u32(smem);
    const int NT = (n_tokens + TILE_M - 1) / TILE_M;

    const int crow = tid >> 1, chalf = tid & 1;   // convert mapping: 2 threads/row

    // prologue: start loading tile `bid` into stage[0]
    prefetch(x, bid, NT, n_tokens, 0, tid, sb);

    // ---- build centers hi/lo in smem (swizzled [n][k] bf16) ----
#pragma unroll
    for (int i = tid; i < N_CLUS * 16; i += THREADS) {     // 16 chunks of 8 per row
        int n = i >> 4, kc = i & 15;
        const float4* cp = (const float4*)(cc + n * N_FEAT + kc * 8);
        float4 ca = cp[0], cb = cp[1];
        uint32_t h[4], l[4]; float dummy = 0.f;
        conv8(ca, cb, h, l, dummy);
        uint32_t off = (uint32_t)(n * 256 + ((kc * 16) ^ ((n & 7) << 4)));
        sts128(sb + OFF_BHI + off, h[0], h[1], h[2], h[3]);
        sts128(sb + OFF_BLO + off, l[0], l[1], l[2], l[3]);
    }
    if (tid < N_CLUS) ((unsigned long long*)(smem + OFF_BEST))[tid] = 0ull;
    __syncthreads();

    // ---- preload Bhi fragments into registers (constant across all tiles) ----
    const int lr = (lane & 7) | (lane & 8);    // ldmatrix row-within-16
    const int lk = lane & 16;                  // 16B column select
    const uint32_t sw = (uint32_t)((lr & 7) << 4);
    const int nb = nh * 32;

    uint32_t bhi[8][4][2];
#pragma unroll
    for (int ks = 0; ks < 8; ++ks) {
#pragma unroll
        for (int np = 0; np < 2; ++np) {
            uint32_t addr = sb + OFF_BHI + (uint32_t)((nb + np * 16 + lr) * 256)
                          + (((uint32_t)(ks * 32 + lk)) ^ sw);
            uint32_t r0, r1, r2, r3;
            ldm4(r0, r1, r2, r3, addr);
            bhi[ks][np * 2][0] = r0;  bhi[ks][np * 2 + 1][0] = r1;
            bhi[ks][np * 2][1] = r2;  bhi[ks][np * 2 + 1][1] = r3;
        }
    }

    // per-tile-constant ldmatrix base addresses
    uint32_t aAh[2], aAl[2], aBl[2];
#pragma unroll
    for (int mi = 0; mi < 2; ++mi) {
        aAh[mi] = sb + OFF_XHI + (uint32_t)((mg * 32 + mi * 16 + lr) * 256);
        aAl[mi] = sb + OFF_XLO + (uint32_t)((mg * 32 + mi * 16 + lr) * 256);
    }
#pragma unroll
    for (int np = 0; np < 2; ++np)
        aBl[np] = sb + OFF_BLO + (uint32_t)((nb + np * 16 + lr) * 256);

    float* x2s = (float*)(smem + OFF_X2);
    unsigned long long* bestk = (unsigned long long*)(smem + OFF_BEST);

    unsigned long long bests[4][2];
#pragma unroll
    for (int ni = 0; ni < 4; ++ni) { bests[ni][0] = 0ull; bests[ni][1] = 0ull; }

    int it = 0;
    for (int t = bid; t < NT; t += GRID_MAIN, ++it) {
        const int base = t * TILE_M;
        const int buf  = it & 1;

        cp_wait0();
        __syncthreads();      // stage[buf] fully visible to all threads

        // ---- convert phase: stage fp32 -> bf16 hi/lo smem + |x|^2 ----
        {
            const bool val = (base + crow) < n_tokens;
            const uint32_t rowb = sb + (uint32_t)(OFF_STAGE + buf * 65536 + crow * 512);
            const int rsw = crow & 31;
            float s = 0.f;
#pragma unroll
            for (int j = 0; j < 8; ++j) {
                float4 a, b;
                lds128(a.x, a.y, a.z, a.w, rowb + (uint32_t)(((chalf * 16 + 2 * j) ^ rsw) << 4));
                lds128(b.x, b.y, b.z, b.w, rowb + (uint32_t)(((chalf * 16 + 2 * j + 1) ^ rsw) << 4));
                if (!val) { a = make_float4(0.f, 0.f, 0.f, 0.f); b = a; }
                uint32_t h[4], l[4];
                conv8(a, b, h, l, s);
                uint32_t off = (uint32_t)(crow * 256 + (((chalf * 8 + j) * 16) ^ ((crow & 7) << 4)));
                sts128(sb + OFF_XHI + off, h[0], h[1], h[2], h[3]);
                sts128(sb + OFF_XLO + off, l[0], l[1], l[2], l[3]);
            }
            s += __shfl_xor_sync(0xFFFFFFFFu, s, 1);
            if (chalf == 0) x2s[crow] = s;
        }

        // issue next tile's cp.async into the other stage buffer (overlaps MMA)
        prefetch(x, t + GRID_MAIN, NT, n_tokens, buf ^ 1, tid, sb);

        __syncthreads();      // bf16 tiles + x2s ready

        // ---- MMA phase ----
        float c[2][4][4];
#pragma unroll
        for (int mi = 0; mi < 2; ++mi)
#pragma unroll
            for (int ni = 0; ni < 4; ++ni)
#pragma unroll
                for (int r = 0; r < 4; ++r) c[mi][ni][r] = 0.f;

#pragma unroll
        for (int ks = 0; ks < 8; ++ks) {
            const uint32_t ko = ((uint32_t)(ks * 32 + lk)) ^ sw;
            uint32_t ah[2][4], al[2][4];
#pragma unroll
            for (int mi = 0; mi < 2; ++mi) {
                ldm4(ah[mi][0], ah[mi][1], ah[mi][2], ah[mi][3], aAh[mi] + ko);
                ldm4(al[mi][0], al[mi][1], al[mi][2], al[mi][3], aAl[mi] + ko);
            }
            uint32_t bl[4][2];
#pragma unroll
            for (int np = 0; np < 2; ++np) {
                uint32_t r0, r1, r2, r3;
                ldm4(r0, r1, r2, r3, aBl[np] + ko);
                bl[np * 2][0] = r0;  bl[np * 2 + 1][0] = r1;
                bl[np * 2][1] = r2;  bl[np * 2 + 1][1] = r3;
            }
#pragma unroll
            for (int mi = 0; mi < 2; ++mi) {
#pragma unroll
                for (int ni = 0; ni < 4; ++ni) {
                    mma16816(c[mi][ni][0], c[mi][ni][1], c[mi][ni][2], c[mi][ni][3],
                             ah[mi][0], ah[mi][1], ah[mi][2], ah[mi][3],
                             bhi[ks][ni][0], bhi[ks][ni][1]);                 // hh
                    mma16816(c[mi][ni][0], c[mi][ni][1], c[mi][ni][2], c[mi][ni][3],
                             al[mi][0], al[mi][1], al[mi][2], al[mi][3],
                             bhi[ks][ni][0], bhi[ks][ni][1]);                 // lh
                    mma16816(c[mi][ni][0], c[mi][ni][1], c[mi][ni][2], c[mi][ni][3],
                             ah[mi][0], ah[mi][1], ah[mi][2], ah[mi][3],
                             bl[ni][0], bl[ni][1]);                           // hl
                }
            }
        }

        // ---- epilogue: fold into per-thread running bests ----
        float h2[2][2];
#pragma unroll
        for (int mi = 0; mi < 2; ++mi)
#pragma unroll
            for (int p = 0; p < 2; ++p)
                h2[mi][p] = 0.5f * x2s[mg * 32 + mi * 16 + (lane >> 2) + p * 8];

#pragma unroll
        for (int ni = 0; ni < 4; ++ni) {
#pragma unroll
            for (int ci = 0; ci < 2; ++ci) {
                unsigned long long bk = bests[ni][ci];
#pragma unroll
                for (int mi = 0; mi < 2; ++mi) {
#pragma unroll
                    for (int p = 0; p < 2; ++p) {
                        int row = mg * 32 + mi * 16 + (lane >> 2) + p * 8;
                        int gidx = base + row;
                        float sc = c[mi][ni][ci + 2 * p] - h2[mi][p];
                        if (gidx < n_tokens) {
                            unsigned long long key =
                                ((unsigned long long)orderf(sc) << 32) |
                                (unsigned long long)(0xFFFFFFFFu - (uint32_t)gidx);
                            if (key > bk) bk = key;
                        }
                    }
                }
                bests[ni][ci] = bk;
            }
        }
        __syncthreads();   // all ldmatrix/x2s reads done before next convert overwrites
    }

    // ---- final reduction: butterfly within column class, atomicMax into smem ----
#pragma unroll
    for (int ni = 0; ni < 4; ++ni) {
#pragma unroll
        for (int ci = 0; ci < 2; ++ci) {
            unsigned long long k = bests[ni][ci];
#pragma unroll
            for (int d = 4; d <= 16; d <<= 1) {
                unsigned long long o = __shfl_xor_sync(0xFFFFFFFFu, k, d);
                if (o > k) k = o;
            }
            if (lane < 4)
                atomicMax(&bestk[nb + ni * 8 + lane * 2 + ci], k);
        }
    }
    __syncthreads();
    if (tid < N_CLUS)
        g_part[(size_t)bid * N_CLUS + tid] = bestk[tid];
}

// ---------------- gather: reduce partials, copy winning rows ----------------
__global__ void gather_k(const float* __restrict__ x, float* __restrict__ out) {
    __shared__ unsigned long long red[256];
    const int c = blockIdx.x, tid = threadIdx.x;
    unsigned long long v = 0ull;
    if (tid < GRID_MAIN) v = g_part[(size_t)tid * N_CLUS + c];
    red[tid] = v;
    __syncthreads();
#pragma unroll
    for (int s = 128; s > 0; s >>= 1) {
        if (tid < s) { unsigned long long o = red[tid + s]; if (o > red[tid]) red[tid] = o; }
        __syncthreads();
    }
    unsigned int gi = 0xFFFFFFFFu - (unsigned int)(red[0] & 0xFFFFFFFFull);
    if (tid < N_FEAT)
        out[c * N_FEAT + tid] = x[(size_t)gi * N_FEAT + tid];
}

// ---------------- launch ----------------
extern "C" void kernel_launch(void* const* d_in, const int* in_sizes, int n_in,
                              void* d_out, int out_size)
{
    const float* x  = (const float*)d_in[0];
    const float* cc = (const float*)d_in[1];
    int n_tokens = in_sizes[0] / N_FEAT;

    cudaFuncSetAttribute(cluster_hmma, cudaFuncAttributeMaxDynamicSharedMemorySize, SMEM_TOTAL);
    cluster_hmma<<<GRID_MAIN, THREADS, SMEM_TOTAL>>>(x, cc, n_tokens);
    gather_k<<<N_CLUS, 256>>>(x, (float*)d_out);
}

// round 5
// speedup vs baseline: 4.3646x; 1.1305x over previous
#include <cuda_runtime.h>
#include <cuda_bf16.h>
#include <cstdint>

#define N_FEAT    128
#define N_CLUS    64
#define TILE_M    128
#define THREADS   256
#define GRID_MAIN 148
#define EPS       1.0f
#define TWOEPS    2.0f
#define NEGINF    (-3.4e38f)

// smem layout (bytes)
#define OFF_STAGE 0          // 2 * 128 rows * 512B fp32, XOR-swizzled 16B chunks
#define OFF_XHI   131072     // 128 rows * 256B bf16 (hi), swizzled
#define OFF_BHI   163840     // 64 rows * 256B bf16 (hi), swizzled
#define OFF_CCF   180224     // 64 * 128 fp32 centers, linear
#define OFF_X2    212992     // 128 floats
#define OFF_BEST  213504     // 64 u64 exact keys
#define SMEM_TOTAL 214016

__device__ unsigned long long g_part[GRID_MAIN * N_CLUS];

// ---------------- helpers ----------------
__device__ __forceinline__ uint32_t smem_u32(const void* p) {
    return (uint32_t)__cvta_generic_to_shared(p);
}
__device__ __forceinline__ uint32_t cvt_bf2(float hi, float lo) {
    uint32_t d;
    asm("cvt.rn.bf16x2.f32 %0, %1, %2;" : "=r"(d) : "f"(hi), "f"(lo)); // low half = lo
    return d;
}
__device__ __forceinline__ uint32_t orderf(float f) {
    uint32_t u = __float_as_uint(f);
    return u ^ (((uint32_t)((int32_t)u >> 31)) | 0x80000000u);
}
__device__ __forceinline__ float inv_orderf(uint32_t k) {
    uint32_t u = (k & 0x80000000u) ? (k ^ 0x80000000u) : ~k;
    return __uint_as_float(u);   // k==0 -> NaN; fmaxf(NaN,x)=x handles bootstrap
}
__device__ __forceinline__ void sts128(uint32_t a, uint32_t x, uint32_t y, uint32_t z, uint32_t w) {
    asm volatile("st.shared.v4.b32 [%0], {%1,%2,%3,%4};" :: "r"(a), "r"(x), "r"(y), "r"(z), "r"(w) : "memory");
}
__device__ __forceinline__ void lds128(float& x, float& y, float& z, float& w, uint32_t a) {
    asm volatile("ld.shared.v4.f32 {%0,%1,%2,%3}, [%4];"
                 : "=f"(x), "=f"(y), "=f"(z), "=f"(w) : "r"(a));
}
__device__ __forceinline__ uint32_t lds32v(uint32_t a) {
    uint32_t d;
    asm volatile("ld.volatile.shared.b32 %0, [%1];" : "=r"(d) : "r"(a));
    return d;
}
__device__ __forceinline__ void ldm4(uint32_t& r0, uint32_t& r1, uint32_t& r2, uint32_t& r3, uint32_t a) {
    asm volatile("ldmatrix.sync.aligned.m8n8.x4.shared.b16 {%0,%1,%2,%3}, [%4];"
                 : "=r"(r0), "=r"(r1), "=r"(r2), "=r"(r3) : "r"(a));
}
__device__ __forceinline__ void mma16816(float& c0, float& c1, float& c2, float& c3,
                                         uint32_t a0, uint32_t a1, uint32_t a2, uint32_t a3,
                                         uint32_t b0, uint32_t b1) {
    asm volatile("mma.sync.aligned.m16n8k16.row.col.f32.bf16.bf16.f32 "
                 "{%0,%1,%2,%3},{%4,%5,%6,%7},{%8,%9},{%0,%1,%2,%3};"
                 : "+f"(c0), "+f"(c1), "+f"(c2), "+f"(c3)
                 : "r"(a0), "r"(a1), "r"(a2), "r"(a3), "r"(b0), "r"(b1));
}
__device__ __forceinline__ void cp16(uint32_t s, const void* g) {
    asm volatile("cp.async.cg.shared.global [%0], [%1], 16;" :: "r"(s), "l"(g));
}
__device__ __forceinline__ void cp_commit() { asm volatile("cp.async.commit_group;"); }
__device__ __forceinline__ void cp_wait0()  { asm volatile("cp.async.wait_group 0;" ::: "memory"); }

extern __shared__ char smem[];

// prefetch one 128x128 fp32 tile into stage buffer b via cp.async
__device__ __forceinline__ void prefetch(const float* __restrict__ x, int t, int NT,
                                         int n_tokens, int b, int tid, uint32_t sb) {
    if (t < NT) {
        const int base = t * TILE_M;
#pragma unroll
        for (int c = 0; c < 16; ++c) {
            int chunk = tid + c * THREADS;      // 0..4095
            int r = chunk >> 5, q = chunk & 31;
            if (base + r < n_tokens)
                cp16(sb + (uint32_t)(OFF_STAGE + b * 65536 + r * 512 + ((q ^ (r & 31)) << 4)),
                     x + (size_t)(base + r) * N_FEAT + q * 4);
        }
    }
    cp_commit();
}

// exact warp-cooperative rescore of (row in tile, cluster)
__device__ __forceinline__ void warp_rescore(uint32_t sb, int buf, int row, int cl, int base,
                                             int lane, const float* x2s,
                                             unsigned long long* bestk) {
    float4 xv, cv;
    lds128(xv.x, xv.y, xv.z, xv.w,
           sb + (uint32_t)(OFF_STAGE + buf * 65536 + row * 512 + (((lane ^ (row & 31)) & 31) << 4)));
    lds128(cv.x, cv.y, cv.z, cv.w,
           sb + (uint32_t)(OFF_CCF + cl * 512 + (lane << 4)));
    float d = xv.x * cv.x + xv.y * cv.y + xv.z * cv.z + xv.w * cv.w;
#pragma unroll
    for (int o = 16; o >= 1; o >>= 1)
        d += __shfl_xor_sync(0xFFFFFFFFu, d, o);
    if (lane == 0) {
        float s = d - 0.5f * x2s[row];
        unsigned long long key =
            ((unsigned long long)orderf(s) << 32) |
            (unsigned long long)(0xFFFFFFFFu - (uint32_t)(base + row));
        atomicMax(&bestk[cl], key);
    }
}

__global__ void __launch_bounds__(THREADS, 1)
cluster_hmma(const float* __restrict__ x, const float* __restrict__ cc, int n_tokens)
{
    const int tid  = threadIdx.x;
    const int lane = tid & 31;
    const int wid  = tid >> 5;
    const int mg   = wid >> 1;     // m-group: rows [mg*32, mg*32+32)
    const int nh   = wid & 1;      // n-half:  cols [nh*32, nh*32+32)
    const int bid  = blockIdx.x;
    const uint32_t sb = smem_u32(smem);
    const int NT = (n_tokens + TILE_M - 1) / TILE_M;

    const int crow = tid >> 1, chalf = tid & 1;   // convert mapping: 2 threads/row

    // prologue: start loading tile `bid` into stage[0]
    prefetch(x, bid, NT, n_tokens, 0, tid, sb);

    // ---- centers: fp32 copy (linear) + bf16-hi swizzled ----
    {
        const float4* c4 = (const float4*)cc;
        float4* f4 = (float4*)(smem + OFF_CCF);
        for (int i = tid; i < N_CLUS * N_FEAT / 4; i += THREADS)
            f4[i] = c4[i];
    }
#pragma unroll
    for (int i = tid; i < N_CLUS * 16; i += THREADS) {   // 16 chunks of 8 per row
        int n = i >> 4, kc = i & 15;
        const float4* cp = (const float4*)(cc + n * N_FEAT + kc * 8);
        float4 ca = cp[0], cb = cp[1];
        uint32_t h0 = cvt_bf2(ca.y, ca.x), h1 = cvt_bf2(ca.w, ca.z);
        uint32_t h2 = cvt_bf2(cb.y, cb.x), h3 = cvt_bf2(cb.w, cb.z);
        uint32_t off = (uint32_t)(n * 256 + ((kc * 16) ^ ((n & 7) << 4)));
        sts128(sb + OFF_BHI + off, h0, h1, h2, h3);
    }
    if (tid < N_CLUS) ((unsigned long long*)(smem + OFF_BEST))[tid] = 0ull;
    __syncthreads();

    // ---- preload Bhi fragments into registers (constant across all tiles) ----
    const int lr = (lane & 7) | (lane & 8);    // ldmatrix row-within-16
    const int lk = lane & 16;                  // 16B column select
    const uint32_t sw = (uint32_t)((lr & 7) << 4);
    const int nb = nh * 32;

    uint32_t bhi[8][4][2];
#pragma unroll
    for (int ks = 0; ks < 8; ++ks) {
#pragma unroll
        for (int np = 0; np < 2; ++np) {
            uint32_t addr = sb + OFF_BHI + (uint32_t)((nb + np * 16 + lr) * 256)
                          + (((uint32_t)(ks * 32 + lk)) ^ sw);
            uint32_t r0, r1, r2, r3;
            ldm4(r0, r1, r2, r3, addr);
            bhi[ks][np * 2][0] = r0;  bhi[ks][np * 2 + 1][0] = r1;
            bhi[ks][np * 2][1] = r2;  bhi[ks][np * 2 + 1][1] = r3;
        }
    }

    uint32_t aAh[2];
#pragma unroll
    for (int mi = 0; mi < 2; ++mi)
        aAh[mi] = sb + OFF_XHI + (uint32_t)((mg * 32 + mi * 16 + lr) * 256);

    float* x2s = (float*)(smem + OFF_X2);
    unsigned long long* bestk = (unsigned long long*)(smem + OFF_BEST);

    int it = 0;
    for (int t = bid; t < NT; t += GRID_MAIN, ++it) {
        const int base = t * TILE_M;
        const int buf  = it & 1;

        cp_wait0();
        __syncthreads();      // stage[buf] fully visible

        // ---- convert: stage fp32 -> bf16-hi smem + |x|^2 ----
        {
            const bool val = (base + crow) < n_tokens;
            const uint32_t rowb = sb + (uint32_t)(OFF_STAGE + buf * 65536 + crow * 512);
            const int rsw = crow & 31;
            float s = 0.f;
#pragma unroll
            for (int j = 0; j < 8; ++j) {
                float4 a, b;
                lds128(a.x, a.y, a.z, a.w, rowb + (uint32_t)(((chalf * 16 + 2 * j) ^ rsw) << 4));
                lds128(b.x, b.y, b.z, b.w, rowb + (uint32_t)(((chalf * 16 + 2 * j + 1) ^ rsw) << 4));
                if (!val) { a = make_float4(0.f, 0.f, 0.f, 0.f); b = a; }
                uint32_t h0 = cvt_bf2(a.y, a.x), h1 = cvt_bf2(a.w, a.z);
                uint32_t h2r = cvt_bf2(b.y, b.x), h3 = cvt_bf2(b.w, b.z);
                s += a.x * a.x + a.y * a.y + a.z * a.z + a.w * a.w;
                s += b.x * b.x + b.y * b.y + b.z * b.z + b.w * b.w;
                uint32_t off = (uint32_t)(crow * 256 + (((chalf * 8 + j) * 16) ^ ((crow & 7) << 4)));
                sts128(sb + OFF_XHI + off, h0, h1, h2r, h3);
            }
            s += __shfl_xor_sync(0xFFFFFFFFu, s, 1);
            if (chalf == 0) x2s[crow] = s;
        }

        // next tile's cp.async into the other stage buffer (overlaps MMA)
        prefetch(x, t + GRID_MAIN, NT, n_tokens, buf ^ 1, tid, sb);

        __syncthreads();      // bf16 tile + x2s ready

        // ---- MMA: hh term only ----
        float c[2][4][4];
#pragma unroll
        for (int mi = 0; mi < 2; ++mi)
#pragma unroll
            for (int ni = 0; ni < 4; ++ni)
#pragma unroll
                for (int r = 0; r < 4; ++r) c[mi][ni][r] = 0.f;

#pragma unroll
        for (int ks = 0; ks < 8; ++ks) {
            const uint32_t ko = ((uint32_t)(ks * 32 + lk)) ^ sw;
            uint32_t ah[2][4];
#pragma unroll
            for (int mi = 0; mi < 2; ++mi)
                ldm4(ah[mi][0], ah[mi][1], ah[mi][2], ah[mi][3], aAh[mi] + ko);
#pragma unroll
            for (int mi = 0; mi < 2; ++mi)
#pragma unroll
                for (int ni = 0; ni < 4; ++ni)
                    mma16816(c[mi][ni][0], c[mi][ni][1], c[mi][ni][2], c[mi][ni][3],
                             ah[mi][0], ah[mi][1], ah[mi][2], ah[mi][3],
                             bhi[ks][ni][0], bhi[ks][ni][1]);
        }

        // ---- epilogue: approx scores, per-warp per-cluster max, threshold, rescue ----
        float h2[2][2];
        bool vld[2][2];
#pragma unroll
        for (int mi = 0; mi < 2; ++mi)
#pragma unroll
            for (int p = 0; p < 2; ++p) {
                int row = mg * 32 + mi * 16 + (lane >> 2) + p * 8;
                h2[mi][p] = 0.5f * x2s[row];
                vld[mi][p] = (base + row) < n_tokens;
            }

        // scores in place: c[mi][ni][ci+2p] := s̃ or -inf
#pragma unroll
        for (int mi = 0; mi < 2; ++mi)
#pragma unroll
            for (int ni = 0; ni < 4; ++ni)
#pragma unroll
                for (int p = 0; p < 2; ++p)
#pragma unroll
                    for (int ci = 0; ci < 2; ++ci) {
                        float sc = c[mi][ni][ci + 2 * p] - h2[mi][p];
                        c[mi][ni][ci + 2 * p] = vld[mi][p] ? sc : NEGINF;
                    }

        // per-warp per-cluster approx max
        float mloc[4][2];
#pragma unroll
        for (int ni = 0; ni < 4; ++ni)
#pragma unroll
            for (int ci = 0; ci < 2; ++ci) {
                float m = fmaxf(fmaxf(c[0][ni][ci], c[0][ni][ci + 2]),
                                fmaxf(c[1][ni][ci], c[1][ni][ci + 2]));
#pragma unroll
                for (int d = 4; d <= 16; d <<= 1)
                    m = fmaxf(m, __shfl_xor_sync(0xFFFFFFFFu, m, d));
                mloc[ni][ci] = m;
            }

        // thresholds
        float thrf[4][2];
#pragma unroll
        for (int ni = 0; ni < 4; ++ni)
#pragma unroll
            for (int ci = 0; ci < 2; ++ci) {
                int cl = nb + ni * 8 + (lane & 3) * 2 + ci;
                uint32_t hi = lds32v(sb + (uint32_t)(OFF_BEST + cl * 8 + 4));
                float b = inv_orderf(hi);                        // NaN if unset
                thrf[ni][ci] = fmaxf(b - EPS, mloc[ni][ci] - TWOEPS);
            }

        // candidate mask: bit = (ni<<3)|(ci<<2)|(p<<1)|mi
        uint32_t myMask = 0;
#pragma unroll
        for (int ni = 0; ni < 4; ++ni)
#pragma unroll
            for (int ci = 0; ci < 2; ++ci)
#pragma unroll
                for (int p = 0; p < 2; ++p)
#pragma unroll
                    for (int mi = 0; mi < 2; ++mi)
                        if (c[mi][ni][ci + 2 * p] >= thrf[ni][ci])
                            myMask |= 1u << ((ni << 3) | (ci << 2) | (p << 1) | mi);

        uint32_t active = __ballot_sync(0xFFFFFFFFu, myMask != 0);
        while (active) {
            int src = __ffs(active) - 1;
            active &= active - 1;
            uint32_t m = __shfl_sync(0xFFFFFFFFu, myMask, src);
            while (m) {
                int b = __ffs(m) - 1;
                m &= m - 1;
                int mi = b & 1, p = (b >> 1) & 1, ci = (b >> 2) & 1, ni = b >> 3;
                int row = mg * 32 + mi * 16 + (src >> 2) + p * 8;
                int cl  = nb + ni * 8 + (src & 3) * 2 + ci;
                warp_rescore(sb, buf, row, cl, base, lane, x2s, bestk);
            }
        }
        __syncthreads();   // all reads of XHI/x2s/stage done before next tile
    }

    // ---- write per-CTA exact results ----
    if (tid < N_CLUS)
        g_part[(size_t)bid * N_CLUS + tid] = bestk[tid];
}

// ---------------- gather: reduce partials, copy winning rows ----------------
__global__ void gather_k(const float* __restrict__ x, float* __restrict__ out) {
    __shared__ unsigned long long red[256];
    const int c = blockIdx.x, tid = threadIdx.x;
    unsigned long long v = 0ull;
    if (tid < GRID_MAIN) v = g_part[(size_t)tid * N_CLUS + c];
    red[tid] = v;
    __syncthreads();
#pragma unroll
    for (int s = 128; s > 0; s >>= 1) {
        if (tid < s) { unsigned long long o = red[tid + s]; if (o > red[tid]) red[tid] = o; }
        __syncthreads();
    }
    unsigned int gi = 0xFFFFFFFFu - (unsigned int)(red[0] & 0xFFFFFFFFull);
    if (tid < N_FEAT)
        out[c * N_FEAT + tid] = x[(size_t)gi * N_FEAT + tid];
}

// ---------------- launch ----------------
extern "C" void kernel_launch(void* const* d_in, const int* in_sizes, int n_in,
                              void* d_out, int out_size)
{
    const float* x  = (const float*)d_in[0];
    const float* cc = (const float*)d_in[1];
    int n_tokens = in_sizes[0] / N_FEAT;

    cudaFuncSetAttribute(cluster_hmma, cudaFuncAttributeMaxDynamicSharedMemorySize, SMEM_TOTAL);
    cluster_hmma<<<GRID_MAIN, THREADS, SMEM_TOTAL>>>(x, cc, n_tokens);
    gather_k<<<N_CLUS, 256>>>(x, (float*)d_out);
}